// round 16
// baseline (speedup 1.0000x reference)
#include <cuda_runtime.h>
#include <cuda_fp16.h>
#include <cstdint>

// ---------------------------------------------------------------------------
// Problem constants
// ---------------------------------------------------------------------------
#define BATCH 256
#define SEQ   256
#define EMB   256
#define HID   1024
#define GATES 4096          // 4*HID
#define SH    (SEQ * HID)   // per-batch stride in out

// Tiling: grid = 64 n-tiles x 2 m-tiles = 128 persistent CTAs, 512 threads
#define THREADS 512
#define TM 128              // CTA M tile (batch)
#define TN 64               // CTA N tile (gate-cols, j-major)
#define KC 64               // K chunk (fp16)
#define NCHUNK (HID / KC)   // 16

// SMEM layout: resident W slice + 3-stage A pipeline + separate D
#define W_OFF   0
#define WCHUNK  8192                    // 64 rows x 128B per k-chunk
#define W_BYTES (NCHUNK * WCHUNK)       // 131072
#define A_OFF   W_BYTES
#define A_STAGE 16384                   // 128 rows x 128B
#define NSTAGE  3
#define D_OFF   (A_OFF + NSTAGE * A_STAGE)      // 180224
#define DS 68                                   // D row stride (floats), %4==0
#define D_BYTES (TM * DS * 4)                   // 34816
#define SMEM_TOTAL (D_OFF + D_BYTES)            // 215040

#define SWZ(off) ((off) ^ (((off) >> 3) & 0x70))

// ---------------------------------------------------------------------------
// Device-global state
// ---------------------------------------------------------------------------
__device__ float g_lp_r[30 * GATES];   // n = j*4 + gate
__device__ float g_sp_r[4 * GATES];
__device__ __half g_W_h[(size_t)GATES * HID];   // row n = j*4+g
__device__ __half g_h[2][(size_t)BATCH * HID];  // h scratch fp16 ping-pong

// Per-producer dataflow flags: chunk c of group g is produced by the 4 CTAs
// bx = 4c..4c+3 (slot = bx&3). Single-writer u64 each, monotonic across
// replays; 4 flags of a chunk share one 128B line for 1-line consumer polls.
struct __align__(128) ChunkFlags { unsigned long long p[4]; char pad[96]; };
__device__ ChunkFlags g_pf[2][NCHUNK];

// ---------------------------------------------------------------------------
// PTX helpers (Ampere-era: valid at compute_103)
// ---------------------------------------------------------------------------
__device__ __forceinline__ uint32_t smem_u32(const void* p) {
    uint32_t a;
    asm("{ .reg .u64 t; cvta.to.shared.u64 t, %1; cvt.u32.u64 %0, t; }"
        : "=r"(a) : "l"(p));
    return a;
}
#define CP16(dst, src) \
    asm volatile("cp.async.cg.shared.global [%0], [%1], 16;" :: "r"(dst), "l"(src))
#define CP_COMMIT() asm volatile("cp.async.commit_group;" ::: "memory")
#define CP_WAIT(n)  asm volatile("cp.async.wait_group %0;" :: "n"(n) : "memory")

__device__ __forceinline__ void ldsm_x4(uint32_t (&r)[4], uint32_t addr) {
    asm volatile("ldmatrix.sync.aligned.m8n8.x4.shared.b16 {%0,%1,%2,%3}, [%4];"
                 : "=r"(r[0]), "=r"(r[1]), "=r"(r[2]), "=r"(r[3]) : "r"(addr));
}
__device__ __forceinline__ void mma_f16(float (&d)[4], const uint32_t (&a)[4],
                                        const uint32_t* b) {
    asm volatile(
        "mma.sync.aligned.m16n8k16.row.col.f32.f16.f16.f32 "
        "{%0,%1,%2,%3}, {%4,%5,%6,%7}, {%8,%9}, {%0,%1,%2,%3};"
        : "+f"(d[0]), "+f"(d[1]), "+f"(d[2]), "+f"(d[3])
        : "r"(a[0]), "r"(a[1]), "r"(a[2]), "r"(a[3]), "r"(b[0]), "r"(b[1]));
}

__device__ __forceinline__ unsigned long long ld_acq(const unsigned long long* p) {
    unsigned long long v;
    asm volatile("ld.acquire.gpu.global.u64 %0, [%1];" : "=l"(v) : "l"(p) : "memory");
    return v;
}
__device__ __forceinline__ void st_rel(unsigned long long* p, unsigned long long v) {
    asm volatile("st.release.gpu.global.u64 [%0], %1;" :: "l"(p), "l"(v) : "memory");
}

// hardware tanh (sm_75+): 1 MUFU op
__device__ __forceinline__ float tanha(float x) {
    float y;
    asm("tanh.approx.f32 %0, %1;" : "=f"(y) : "f"(x));
    return y;
}
__device__ __forceinline__ float siga(float x) {
    return fmaf(tanha(0.5f * x), 0.5f, 0.5f);
}

// ---------------------------------------------------------------------------
// Dummy kernel: steers ncu capture (-s 5) onto lstm_persist
// ---------------------------------------------------------------------------
__global__ void dummy_kernel() {}

// ---------------------------------------------------------------------------
// Precompute 1: projection tables — one block per (entry, 256-gate slab)
// ---------------------------------------------------------------------------
__global__ void __launch_bounds__(256)
proj_kernel(const float* __restrict__ letter_emb,
            const float* __restrict__ state_emb,
            const float* __restrict__ W_ih,
            const float* __restrict__ b_ih,
            const float* __restrict__ b_hh) {
    __shared__ float emb[EMB];
    const int tid = threadIdx.x;
    const int e = blockIdx.y;
    const bool is_letter = (e < 30);
    const float* __restrict__ src = is_letter ? (letter_emb + (size_t)e * EMB)
                                              : (state_emb + (size_t)(e - 30) * EMB);
    emb[tid] = src[tid];
    __syncthreads();

    const int r = blockIdx.x * 256 + tid;        // original gate row
    const float* __restrict__ w = W_ih + (size_t)r * (2 * EMB) + (is_letter ? 0 : EMB);

    float a0 = 0.f, a1 = 0.f, a2 = 0.f, a3 = 0.f;
    #pragma unroll
    for (int k = 0; k < EMB; k += 4) {
        float4 wv = *(const float4*)(w + k);
        a0 += wv.x * emb[k + 0];
        a1 += wv.y * emb[k + 1];
        a2 += wv.z * emb[k + 2];
        a3 += wv.w * emb[k + 3];
    }
    float s = (a0 + a1) + (a2 + a3);

    const int gate = r >> 10, j = r & 1023;
    const int n = j * 4 + gate;
    if (is_letter) {
        g_lp_r[e * GATES + n] = s;
    } else {
        g_sp_r[(e - 30) * GATES + n] = s + b_ih[r] + b_hh[r];
    }
}

// ---------------------------------------------------------------------------
// Precompute 2: W_hh reorder + fp16 convert
// ---------------------------------------------------------------------------
__global__ void wconv_kernel(const float* __restrict__ W_hh) {
    size_t idx = (size_t)blockIdx.x * blockDim.x + threadIdx.x;
    size_t total = (size_t)GATES * HID;
    for (; idx < total; idx += (size_t)gridDim.x * blockDim.x) {
        int n = (int)(idx >> 10);
        int k = (int)(idx & 1023);
        int j = n >> 2, g = n & 3;
        g_W_h[idx] = __float2half(W_hh[((size_t)g * HID + j) * HID + k]);
    }
}

// ---------------------------------------------------------------------------
// Fragment set for one k16 slice (warp tile 32x16)
// ---------------------------------------------------------------------------
struct Frags {
    uint32_t ah[2][4];   // two m16 frags
    uint32_t bh[2][2];   // two n8 frags
};

// ---------------------------------------------------------------------------
// Persistent LSTM kernel: per-producer dataflow flags, rotated chunk order
// ---------------------------------------------------------------------------
__global__ void __launch_bounds__(THREADS, 1)
lstm_persist(const int* __restrict__ lseq,
             const int* __restrict__ sseq,
             float* __restrict__ out) {
    extern __shared__ char smem[];
    const int tid  = threadIdx.x;
    const int wid  = tid >> 5;
    const int lane = tid & 31;
    const int wm   = wid & 3;      // 0..3 m-warps (32 rows each)
    const int wn   = wid >> 2;     // 0..3 n-warps (16 cols each)
    const int grp  = blockIdx.y;   // m-group; groups fully independent
    const int m0   = grp * TM;
    const int bx   = blockIdx.x;
    const int n0c  = bx * TN;
    const int j0   = n0c >> 2;     // 16 j's per CTA
    const int mychunk = bx >> 2;   // chunk this CTA produces into
    const int myslot  = bx & 3;

    float* __restrict__ out_h = out;
    float* __restrict__ out_c = out + (size_t)BATCH * SH;

    const uint32_t sb = smem_u32(smem);
    const int g_  = lane >> 3;
    const int lr_ = lane & 7;

    // monotonic base: own single-writer flag is pristine until MY first post
    unsigned long long base = 0;
    if (tid == 0)
        base = ld_acq(&g_pf[grp][mychunk].p[myslot]);

    // ---- load resident W slice: 16 chunks x [64 rows x 128B] ----
    {
        const __half* __restrict__ wsrc = g_W_h + (size_t)n0c * HID;
        #pragma unroll
        for (int ch = 0; ch < NCHUNK; ++ch) {
            int r = tid >> 3, c = tid & 7;       // 512 items per chunk
            uint32_t dst = sb + W_OFF + ch * WCHUNK
                         + (uint32_t)SWZ(r * 128 + c * 16);
            CP16(dst, wsrc + (size_t)r * HID + ch * KC + c * 8);
        }
        CP_COMMIT();
        CP_WAIT(0);
        __syncthreads();
    }

    // post my chunk flag for step tpost (tid0, after syncthreads)
    auto post = [&](int tpost) {
        __threadfence();
        st_rel(&g_pf[grp][mychunk].p[myslot],
               base + (unsigned long long)(tpost + 1));
    };
    // blocking wait: all 4 producers of chunk c posted >= tgt (tid0 only)
    auto wait4 = [&](int c, unsigned long long tgt) {
        const unsigned long long* p = &g_pf[grp][c].p[0];
        for (;;) {
            unsigned long long v0 = ld_acq(p + 0), v1 = ld_acq(p + 1);
            unsigned long long v2 = ld_acq(p + 2), v3 = ld_acq(p + 3);
            unsigned long long mn = v0 < v1 ? v0 : v1;
            unsigned long long mn2 = v2 < v3 ? v2 : v3;
            if ((mn < mn2 ? mn : mn2) >= tgt) break;
            __nanosleep(20);
        }
    };

    // ---- t = 0: tables only; init register cell state (same (r,q) map) ----
    float cs[4];
    {
        __half* __restrict__ hw = g_h[0];
        #pragma unroll
        for (int i = 0; i < 4; ++i) {
            int id = tid + i * THREADS;
            int r = id >> 4, q = id & 15;
            int b = m0 + r, j = j0 + q;
            int l  = lseq[b * SEQ];
            int st = sseq[b * SEQ];
            const float4 L = *(const float4*)&g_lp_r[(size_t)l  * GATES + (size_t)j * 4];
            const float4 S = *(const float4*)&g_sp_r[(size_t)st * GATES + (size_t)j * 4];
            float ig = siga(L.x + S.x);
            float gg = tanha(L.z + S.z);
            float og = siga(L.w + S.w);
            float c = ig * gg;
            float h = og * tanha(c);
            out_h[(size_t)b * SH + j] = h;
            out_c[(size_t)b * SH + j] = c;
            hw[(size_t)b * HID + j] = __float2half(h);
            cs[i] = c;
        }
    }
    __syncthreads();
    if (tid == 0) post(0);

    // ---- main time loop (no global barrier; per-chunk dataflow) ----
    for (int t = 1; t < SEQ; ++t) {
        const __half* __restrict__ ha = g_h[(t & 1) ^ 1] + (size_t)m0 * HID;
        __half* __restrict__ hw = g_h[t & 1];
        const unsigned long long tgt = base + (unsigned long long)t;

        // --- prefetch epilogue gathers (independent of h) ---
        float4 Lv[4], Sv[4];
        #pragma unroll
        for (int i = 0; i < 4; ++i) {
            int id = tid + i * THREADS;
            int r = id >> 4, q = id & 15;
            int b = m0 + r, j = j0 + q;
            int l  = lseq[b * SEQ + t];
            int st = sseq[b * SEQ + t];
            Lv[i] = *(const float4*)&g_lp_r[(size_t)l  * GATES + (size_t)j * 4];
            Sv[i] = *(const float4*)&g_sp_r[(size_t)st * GATES + (size_t)j * 4];
        }

        float acc[2][2][4];
        #pragma unroll
        for (int ms = 0; ms < 2; ++ms)
            #pragma unroll
            for (int ns = 0; ns < 2; ++ns)
                #pragma unroll
                for (int q = 0; q < 4; ++q) acc[ms][ns][q] = 0.0f;

        // A chunk loader: 2 x 16B cp.async per thread (1024 items)
        auto load_chunk = [&](int stage, int k0) {
            uint32_t buf = sb + A_OFF + stage * A_STAGE;
            #pragma unroll
            for (int i = 0; i < 2; ++i) {
                int id = tid + i * THREADS;
                int r = id >> 3, c = id & 7;
                uint32_t dst = buf + (uint32_t)SWZ(r * 128 + c * 16);
                CP16(dst, ha + (size_t)r * HID + k0 + c * 8);
            }
        };

        // frag loader: A from stage, B from resident W chunk (phys index)
        auto load_frags = [&](Frags& f, int stage, int pc, int k16) {
            uint32_t abase = sb + A_OFF + stage * A_STAGE;
            uint32_t wbase = sb + W_OFF + pc * WCHUNK;
            #pragma unroll
            for (int ms = 0; ms < 2; ++ms) {
                int r = wm * 32 + ms * 16 + lr_ + ((g_ & 1) << 3);
                int c16 = k16 * 2 + (g_ >> 1);
                ldsm_x4(f.ah[ms], abase + (uint32_t)SWZ(r * 128 + c16 * 16));
            }
            {
                int r = wn * 16 + lr_ + ((g_ >> 1) << 3);
                int c16 = k16 * 2 + (g_ & 1);
                uint32_t tmp[4];
                ldsm_x4(tmp, wbase + (uint32_t)SWZ(r * 128 + c16 * 16));
                f.bh[0][0] = tmp[0]; f.bh[0][1] = tmp[1];
                f.bh[1][0] = tmp[2]; f.bh[1][1] = tmp[3];
            }
        };
        auto mma_all = [&](const Frags& f) {
            #pragma unroll
            for (int ms = 0; ms < 2; ++ms)
                #pragma unroll
                for (int ns = 0; ns < 2; ++ns)
                    mma_f16(acc[ms][ns], f.ah[ms], f.bh[ns]);
        };

        // prologue: wait own-rotated chunks 0,1 (own + near siblings first)
        const int p0 = mychunk;
        const int p1 = (mychunk + 1) & 15;
        if (tid == 0) { wait4(p0, tgt); wait4(p1, tgt); }
        __syncthreads();
        load_chunk(0, p0 * KC);
        CP_COMMIT();
        load_chunk(1, p1 * KC);
        CP_COMMIT();

        Frags f[2];
        int stage_w = 2, stage_r = 0;

        for (int kc = 0; kc < NCHUNK; ++kc) {
            const int pc_next = (mychunk + kc + 2) & 15;
            const bool need = (kc + 2 < NCHUNK);
            // early flag read: overlaps CP_WAIT latency
            unsigned long long v0 = 0, v1 = 0, v2 = 0, v3 = 0;
            if (tid == 0 && need) {
                const unsigned long long* p = &g_pf[grp][pc_next].p[0];
                v0 = ld_acq(p + 0); v1 = ld_acq(p + 1);
                v2 = ld_acq(p + 2); v3 = ld_acq(p + 3);
            }
            CP_WAIT(1);
            if (tid == 0 && need) {
                unsigned long long mn  = v0 < v1 ? v0 : v1;
                unsigned long long mn2 = v2 < v3 ? v2 : v3;
                if ((mn < mn2 ? mn : mn2) < tgt) wait4(pc_next, tgt);
            }
            __syncthreads();
            if (need)
                load_chunk(stage_w, pc_next * KC);
            CP_COMMIT();   // possibly empty: uniform wait arithmetic

            const int pc = (mychunk + kc) & 15;
            load_frags(f[0], stage_r, pc, 0);
            #pragma unroll
            for (int k16 = 0; k16 < 4; ++k16) {
                if (k16 < 3) load_frags(f[(k16 + 1) & 1], stage_r, pc, k16 + 1);
                mma_all(f[k16 & 1]);
            }
            stage_r = (stage_r == 2) ? 0 : stage_r + 1;
            stage_w = (stage_w == 2) ? 0 : stage_w + 1;
        }

        // ---- epilogue: acc -> separate smem D ----
        float* D = (float*)(smem + D_OFF);
        {
            const int wrow = lane >> 2;
            const int wcol = (lane & 3) * 2;
            #pragma unroll
            for (int ms = 0; ms < 2; ++ms)
                #pragma unroll
                for (int ns = 0; ns < 2; ++ns) {
                    int r0 = wm * 32 + ms * 16 + wrow;
                    int cc = wn * 16 + ns * 8 + wcol;
                    *(float2*)&D[r0 * DS + cc]       = make_float2(acc[ms][ns][0], acc[ms][ns][1]);
                    *(float2*)&D[(r0 + 8) * DS + cc] = make_float2(acc[ms][ns][2], acc[ms][ns][3]);
                }
        }
        __syncthreads();

        // compute gates (hw tanh); publish hw FIRST, keep h/c for out
        float hs_[4];
        #pragma unroll
        for (int i = 0; i < 4; ++i) {
            int id = tid + i * THREADS;
            int r = id >> 4, q = id & 15;
            int b = m0 + r, j = j0 + q;
            float4 z = *(const float4*)&D[r * DS + q * 4];
            float zi = z.x + Lv[i].x + Sv[i].x;
            float zf = z.y + Lv[i].y + Sv[i].y;
            float zg = z.z + Lv[i].z + Sv[i].z;
            float zo = z.w + Lv[i].w + Sv[i].w;
            float ig = siga(zi), fg = siga(zf);
            float gg = tanha(zg), og = siga(zo);
            float c = fg * cs[i] + ig * gg;
            float h = og * tanha(c);
            cs[i] = c;
            hs_[i] = h;
            hw[(size_t)b * HID + j] = __float2half(h);
        }

        // post my chunk (release h(t) slice); out stores overlap consumers
        __syncthreads();
        if (tid == 0) post(t);
        #pragma unroll
        for (int i = 0; i < 4; ++i) {
            int id = tid + i * THREADS;
            int r = id >> 4, q = id & 15;
            int b = m0 + r, j = j0 + q;
            out_h[(size_t)b * SH + (size_t)t * HID + j] = hs_[i];
            out_c[(size_t)b * SH + (size_t)t * HID + j] = cs[i];
        }
    }
}

// ---------------------------------------------------------------------------
extern "C" void kernel_launch(void* const* d_in, const int* in_sizes, int n_in,
                              void* d_out, int out_size) {
    const int*   lseq = (const int*)d_in[0];
    const int*   sseq = (const int*)d_in[1];
    const float* lemb = (const float*)d_in[2];
    const float* semb = (const float*)d_in[3];
    const float* W_ih = (const float*)d_in[4];
    const float* W_hh = (const float*)d_in[5];
    const float* b_ih = (const float*)d_in[6];
    const float* b_hh = (const float*)d_in[7];
    float* out = (float*)d_out;

    static bool attr_set = false;
    if (!attr_set) {
        cudaFuncSetAttribute(lstm_persist,
                             cudaFuncAttributeMaxDynamicSharedMemorySize, SMEM_TOTAL);
        attr_set = true;
    }

    // 3 dummies steer ncu (-s 5 -c 1): 6th launch = lstm_persist
    dummy_kernel<<<1, 32>>>();
    dummy_kernel<<<1, 32>>>();
    dummy_kernel<<<1, 32>>>();

    proj_kernel<<<dim3(16, 34), 256>>>(lemb, semb, W_ih, b_ih, b_hh);
    wconv_kernel<<<2048, 256>>>(W_hh);

    lstm_persist<<<dim3(64, 2), THREADS, SMEM_TOTAL>>>(lseq, sseq, out);
}

// round 17
// speedup vs baseline: 2.2588x; 2.2588x over previous
#include <cuda_runtime.h>
#include <cuda_fp16.h>
#include <cstdint>

// ---------------------------------------------------------------------------
// Problem constants
// ---------------------------------------------------------------------------
#define BATCH 256
#define SEQ   256
#define EMB   256
#define HID   1024
#define GATES 4096          // 4*HID
#define SH    (SEQ * HID)   // per-batch stride in out

// Tiling: grid = 64 n-tiles x 2 m-tiles = 128 persistent CTAs, 512 threads
// Warp layout: 4m x 2n x 2k  (warp tile 32 rows x 32 cols x half-K)
#define THREADS 512
#define TM 128              // CTA M tile (batch)
#define TN 64               // CTA N tile (gate-cols, j-major)
#define KC 64               // K chunk (fp16)
#define NCHUNK (HID / KC)   // 16

// SMEM layout: resident W slice + 3-stage A pipeline + separate D
#define W_OFF   0
#define WCHUNK  8192                    // 64 rows x 128B per k-chunk
#define W_BYTES (NCHUNK * WCHUNK)       // 131072
#define A_OFF   W_BYTES
#define A_STAGE 16384                   // 128 rows x 128B
#define NSTAGE  3
#define D_OFF   (A_OFF + NSTAGE * A_STAGE)      // 180224
#define DS 68                                   // D row stride (floats), %4==0
#define D_BYTES (TM * DS * 4)                   // 34816
#define SMEM_TOTAL (D_OFF + D_BYTES)            // 215040

#define SWZ(off) ((off) ^ (((off) >> 3) & 0x70))

// ---------------------------------------------------------------------------
// Device-global state
// ---------------------------------------------------------------------------
__device__ float g_lp_r[30 * GATES];   // n = j*4 + gate
__device__ float g_sp_r[4 * GATES];
__device__ __half g_W_h[(size_t)GATES * HID];   // row n = j*4+g
__device__ __half g_h[2][(size_t)BATCH * HID];  // h scratch fp16 ping-pong

// Tree barrier: 4 sub-counters per group (16 arrivals each) + 1 flag per
// group (bumped 4x per step). All monotonic, own cache lines, replay-safe.
struct __align__(128) BarLine { unsigned long long v; char pad[120]; };
__device__ BarLine g_sub[2][4];
__device__ BarLine g_flag[2];

// ---------------------------------------------------------------------------
// PTX helpers (Ampere-era: valid at compute_103)
// ---------------------------------------------------------------------------
__device__ __forceinline__ uint32_t smem_u32(const void* p) {
    uint32_t a;
    asm("{ .reg .u64 t; cvta.to.shared.u64 t, %1; cvt.u32.u64 %0, t; }"
        : "=r"(a) : "l"(p));
    return a;
}
#define CP16(dst, src) \
    asm volatile("cp.async.cg.shared.global [%0], [%1], 16;" :: "r"(dst), "l"(src))
#define CP_COMMIT() asm volatile("cp.async.commit_group;" ::: "memory")
#define CP_WAIT(n)  asm volatile("cp.async.wait_group %0;" :: "n"(n) : "memory")

__device__ __forceinline__ void ldsm_x4(uint32_t (&r)[4], uint32_t addr) {
    asm volatile("ldmatrix.sync.aligned.m8n8.x4.shared.b16 {%0,%1,%2,%3}, [%4];"
                 : "=r"(r[0]), "=r"(r[1]), "=r"(r[2]), "=r"(r[3]) : "r"(addr));
}
__device__ __forceinline__ void mma_f16(float (&d)[4], const uint32_t (&a)[4],
                                        const uint32_t* b) {
    asm volatile(
        "mma.sync.aligned.m16n8k16.row.col.f32.f16.f16.f32 "
        "{%0,%1,%2,%3}, {%4,%5,%6,%7}, {%8,%9}, {%0,%1,%2,%3};"
        : "+f"(d[0]), "+f"(d[1]), "+f"(d[2]), "+f"(d[3])
        : "r"(a[0]), "r"(a[1]), "r"(a[2]), "r"(a[3]), "r"(b[0]), "r"(b[1]));
}

// hardware tanh (sm_75+): 1 MUFU op
__device__ __forceinline__ float tanha(float x) {
    float y;
    asm("tanh.approx.f32 %0, %1;" : "=f"(y) : "f"(x));
    return y;
}
__device__ __forceinline__ float siga(float x) {
    return fmaf(tanha(0.5f * x), 0.5f, 0.5f);
}

// ---------------------------------------------------------------------------
// Dummy kernel: steers ncu capture (-s 5) onto lstm_persist
// ---------------------------------------------------------------------------
__global__ void dummy_kernel() {}

// ---------------------------------------------------------------------------
// Precompute 1: projection tables — one block per (entry, 256-gate slab)
// ---------------------------------------------------------------------------
__global__ void __launch_bounds__(256)
proj_kernel(const float* __restrict__ letter_emb,
            const float* __restrict__ state_emb,
            const float* __restrict__ W_ih,
            const float* __restrict__ b_ih,
            const float* __restrict__ b_hh) {
    __shared__ float emb[EMB];
    const int tid = threadIdx.x;
    const int e = blockIdx.y;
    const bool is_letter = (e < 30);
    const float* __restrict__ src = is_letter ? (letter_emb + (size_t)e * EMB)
                                              : (state_emb + (size_t)(e - 30) * EMB);
    emb[tid] = src[tid];
    __syncthreads();

    const int r = blockIdx.x * 256 + tid;        // original gate row
    const float* __restrict__ w = W_ih + (size_t)r * (2 * EMB) + (is_letter ? 0 : EMB);

    float a0 = 0.f, a1 = 0.f, a2 = 0.f, a3 = 0.f;
    #pragma unroll
    for (int k = 0; k < EMB; k += 4) {
        float4 wv = *(const float4*)(w + k);
        a0 += wv.x * emb[k + 0];
        a1 += wv.y * emb[k + 1];
        a2 += wv.z * emb[k + 2];
        a3 += wv.w * emb[k + 3];
    }
    float s = (a0 + a1) + (a2 + a3);

    const int gate = r >> 10, j = r & 1023;
    const int n = j * 4 + gate;
    if (is_letter) {
        g_lp_r[e * GATES + n] = s;
    } else {
        g_sp_r[(e - 30) * GATES + n] = s + b_ih[r] + b_hh[r];
    }
}

// ---------------------------------------------------------------------------
// Precompute 2: W_hh reorder + fp16 convert
// ---------------------------------------------------------------------------
__global__ void wconv_kernel(const float* __restrict__ W_hh) {
    size_t idx = (size_t)blockIdx.x * blockDim.x + threadIdx.x;
    size_t total = (size_t)GATES * HID;
    for (; idx < total; idx += (size_t)gridDim.x * blockDim.x) {
        int n = (int)(idx >> 10);
        int k = (int)(idx & 1023);
        int j = n >> 2, g = n & 3;
        g_W_h[idx] = __float2half(W_hh[((size_t)g * HID + j) * HID + k]);
    }
}

// ---------------------------------------------------------------------------
// Fragment set for one k16 slice (warp tile 32 x 32)
// ---------------------------------------------------------------------------
struct Frags {
    uint32_t ah[2][4];   // two m16 frags
    uint32_t bh[4][2];   // four n8 frags
};

// ---------------------------------------------------------------------------
// Persistent LSTM kernel: 4m x 2n x 2k warp layout (halved SMEM redundancy)
// ---------------------------------------------------------------------------
__global__ void __launch_bounds__(THREADS, 1)
lstm_persist(const int* __restrict__ lseq,
             const int* __restrict__ sseq,
             float* __restrict__ out) {
    extern __shared__ char smem[];
    const int tid  = threadIdx.x;
    const int wid  = tid >> 5;
    const int lane = tid & 31;
    const int wm   = wid & 3;         // 0..3 m-warps (32 rows each)
    const int wn   = (wid >> 2) & 1;  // 0..1 n-warps (32 cols each)
    const int wk   = wid >> 3;        // 0..1 k-warps (2 k16 each per chunk)
    const int grp  = blockIdx.y;      // m-group; groups fully independent
    const int m0   = grp * TM;
    const int n0c  = blockIdx.x * TN;
    const int j0   = n0c >> 2;        // 16 j's per CTA
    const int sub  = blockIdx.x & 3;

    float* __restrict__ out_h = out;
    float* __restrict__ out_c = out + (size_t)BATCH * SH;

    const uint32_t sb = smem_u32(smem);
    const int g_  = lane >> 3;
    const int lr_ = lane & 7;

    // barrier flag base (read before this group's first arrive)
    unsigned long long flag_base = 0;
    if (tid == 0)
        flag_base = *((volatile unsigned long long*)&g_flag[grp].v);

    // ---- load resident W slice: 16 chunks x [64 rows x 128B] ----
    {
        const __half* __restrict__ wsrc = g_W_h + (size_t)n0c * HID;
        #pragma unroll
        for (int ch = 0; ch < NCHUNK; ++ch) {
            int r = tid >> 3, c = tid & 7;       // 512 items per chunk
            uint32_t dst = sb + W_OFF + ch * WCHUNK
                         + (uint32_t)SWZ(r * 128 + c * 16);
            CP16(dst, wsrc + (size_t)r * HID + ch * KC + c * 8);
        }
        CP_COMMIT();
        CP_WAIT(0);
        __syncthreads();
    }

    // tree-barrier arrive (tid 0 only; caller handles syncs/fence)
    auto bar_arrive = [&]() {
        unsigned long long old = atomicAdd(&g_sub[grp][sub].v, 1ULL);
        if ((old & 15ULL) == 15ULL) atomicAdd(&g_flag[grp].v, 1ULL);
    };

    // ---- t = 0: tables only; init register cell state (same (r,q) map) ----
    float cs[4];
    {
        __half* __restrict__ hw = g_h[0];
        #pragma unroll
        for (int i = 0; i < 4; ++i) {
            int id = tid + i * THREADS;
            int r = id >> 4, q = id & 15;
            int b = m0 + r, j = j0 + q;
            int l  = lseq[b * SEQ];
            int st = sseq[b * SEQ];
            const float4 L = *(const float4*)&g_lp_r[(size_t)l  * GATES + (size_t)j * 4];
            const float4 S = *(const float4*)&g_sp_r[(size_t)st * GATES + (size_t)j * 4];
            float ig = siga(L.x + S.x);
            float gg = tanha(L.z + S.z);
            float og = siga(L.w + S.w);
            float c = ig * gg;
            float h = og * tanha(c);
            out_h[(size_t)b * SH + j] = h;
            out_c[(size_t)b * SH + j] = c;
            hw[(size_t)b * HID + j] = __float2half(h);
            cs[i] = c;
        }
    }
    __syncthreads();
    if (tid == 0) {
        __threadfence();
        bar_arrive();
        while (*((volatile unsigned long long*)&g_flag[grp].v) < flag_base + 4ULL)
            __nanosleep(20);
        __threadfence();
    }
    __syncthreads();

    // ---- main time loop ----
    for (int t = 1; t < SEQ; ++t) {
        const __half* __restrict__ ha = g_h[(t & 1) ^ 1] + (size_t)m0 * HID;
        __half* __restrict__ hw = g_h[t & 1];

        float acc[2][4][4];   // [ms][ns][quad] — warp tile 32x32, half-K
        #pragma unroll
        for (int ms = 0; ms < 2; ++ms)
            #pragma unroll
            for (int ns = 0; ns < 4; ++ns)
                #pragma unroll
                for (int q = 0; q < 4; ++q) acc[ms][ns][q] = 0.0f;

        // A chunk loader: 2 x 16B cp.async per thread (1024 items)
        auto load_chunk = [&](int stage, int k0) {
            uint32_t buf = sb + A_OFF + stage * A_STAGE;
            #pragma unroll
            for (int i = 0; i < 2; ++i) {
                int id = tid + i * THREADS;
                int r = id >> 3, c = id & 7;
                uint32_t dst = buf + (uint32_t)SWZ(r * 128 + c * 16);
                CP16(dst, ha + (size_t)r * HID + k0 + c * 8);
            }
        };

        // frag loader: A from stage, B from resident W chunk.
        // This warp's k16 index = wk*2 + kh  (kh = 0,1)
        auto load_frags = [&](Frags& f, int stage, int kc, int kh) {
            const int k16 = wk * 2 + kh;
            uint32_t abase = sb + A_OFF + stage * A_STAGE;
            uint32_t wbase = sb + W_OFF + kc * WCHUNK;
            #pragma unroll
            for (int ms = 0; ms < 2; ++ms) {
                int r = wm * 32 + ms * 16 + lr_ + ((g_ & 1) << 3);
                int c16 = k16 * 2 + (g_ >> 1);
                ldsm_x4(f.ah[ms], abase + (uint32_t)SWZ(r * 128 + c16 * 16));
            }
            #pragma unroll
            for (int np = 0; np < 2; ++np) {
                int r = wn * 32 + np * 16 + lr_ + ((g_ >> 1) << 3);
                int c16 = k16 * 2 + (g_ & 1);
                uint32_t tmp[4];
                ldsm_x4(tmp, wbase + (uint32_t)SWZ(r * 128 + c16 * 16));
                f.bh[np * 2 + 0][0] = tmp[0]; f.bh[np * 2 + 0][1] = tmp[1];
                f.bh[np * 2 + 1][0] = tmp[2]; f.bh[np * 2 + 1][1] = tmp[3];
            }
        };
        auto mma_all = [&](const Frags& f) {
            #pragma unroll
            for (int ms = 0; ms < 2; ++ms)
                #pragma unroll
                for (int ns = 0; ns < 4; ++ns)
                    mma_f16(acc[ms][ns], f.ah[ms], f.bh[ns]);
        };

        // prologue: stages 0, 1 in flight
        load_chunk(0, 0);
        CP_COMMIT();
        load_chunk(1, KC);
        CP_COMMIT();

        Frags f[2];
        int stage_w = 2, stage_r = 0;

        for (int kc = 0; kc < NCHUNK; ++kc) {
            CP_WAIT(1);
            __syncthreads();
            if (kc + 2 < NCHUNK)
                load_chunk(stage_w, (kc + 2) * KC);
            CP_COMMIT();   // possibly empty: uniform wait arithmetic

            load_frags(f[0], stage_r, kc, 0);
            load_frags(f[1], stage_r, kc, 1);
            mma_all(f[0]);
            mma_all(f[1]);

            stage_r = (stage_r == 2) ? 0 : stage_r + 1;
            stage_w = (stage_w == 2) ? 0 : stage_w + 1;
        }

        // ---- epilogue: 2-way k reduction through smem D ----
        float* D = (float*)(smem + D_OFF);
        const int wrow = lane >> 2;
        const int wcol = (lane & 3) * 2;
        if (wk == 0) {
            #pragma unroll
            for (int ms = 0; ms < 2; ++ms)
                #pragma unroll
                for (int ns = 0; ns < 4; ++ns) {
                    int r0 = wm * 32 + ms * 16 + wrow;
                    int cc = wn * 32 + ns * 8 + wcol;
                    *(float2*)&D[r0 * DS + cc]       = make_float2(acc[ms][ns][0], acc[ms][ns][1]);
                    *(float2*)&D[(r0 + 8) * DS + cc] = make_float2(acc[ms][ns][2], acc[ms][ns][3]);
                }
        }
        __syncthreads();
        if (wk == 1) {
            #pragma unroll
            for (int ms = 0; ms < 2; ++ms)
                #pragma unroll
                for (int ns = 0; ns < 4; ++ns) {
                    int r0 = wm * 32 + ms * 16 + wrow;
                    int cc = wn * 32 + ns * 8 + wcol;
                    float2 v0 = *(float2*)&D[r0 * DS + cc];
                    float2 v1 = *(float2*)&D[(r0 + 8) * DS + cc];
                    v0.x += acc[ms][ns][0]; v0.y += acc[ms][ns][1];
                    v1.x += acc[ms][ns][2]; v1.y += acc[ms][ns][3];
                    *(float2*)&D[r0 * DS + cc]       = v0;
                    *(float2*)&D[(r0 + 8) * DS + cc] = v1;
                }
        }
        __syncthreads();

        // compute gates (hw tanh); publish hw FIRST, keep h/c for out
        float hs_[4];
        #pragma unroll
        for (int i = 0; i < 4; ++i) {
            int id = tid + i * THREADS;
            int r = id >> 4, q = id & 15;
            int b = m0 + r, j = j0 + q;
            int l  = lseq[b * SEQ + t];
            int st = sseq[b * SEQ + t];
            const float4 L = *(const float4*)&g_lp_r[(size_t)l  * GATES + (size_t)j * 4];
            const float4 S = *(const float4*)&g_sp_r[(size_t)st * GATES + (size_t)j * 4];
            float4 z = *(const float4*)&D[r * DS + q * 4];
            float zi = z.x + L.x + S.x;
            float zf = z.y + L.y + S.y;
            float zg = z.z + L.z + S.z;
            float zo = z.w + L.w + S.w;
            float ig = siga(zi), fg = siga(zf);
            float gg = tanha(zg), og = siga(zo);
            float c = fg * cs[i] + ig * gg;
            float h = og * tanha(c);
            cs[i] = c;
            hs_[i] = h;
            hw[(size_t)b * HID + j] = __float2half(h);
        }

        // arrive early; out stores overlap the spin
        __syncthreads();
        if (tid == 0) {
            __threadfence();
            bar_arrive();
        }
        #pragma unroll
        for (int i = 0; i < 4; ++i) {
            int id = tid + i * THREADS;
            int r = id >> 4, q = id & 15;
            int b = m0 + r, j = j0 + q;
            out_h[(size_t)b * SH + (size_t)t * HID + j] = hs_[i];
            out_c[(size_t)b * SH + (size_t)t * HID + j] = cs[i];
        }
        if (t < SEQ - 1) {
            if (tid == 0) {
                unsigned long long target = flag_base + 4ULL * (unsigned long long)(t + 1);
                while (*((volatile unsigned long long*)&g_flag[grp].v) < target)
                    __nanosleep(20);
                __threadfence();
            }
            __syncthreads();
        }
    }
}

// ---------------------------------------------------------------------------
extern "C" void kernel_launch(void* const* d_in, const int* in_sizes, int n_in,
                              void* d_out, int out_size) {
    const int*   lseq = (const int*)d_in[0];
    const int*   sseq = (const int*)d_in[1];
    const float* lemb = (const float*)d_in[2];
    const float* semb = (const float*)d_in[3];
    const float* W_ih = (const float*)d_in[4];
    const float* W_hh = (const float*)d_in[5];
    const float* b_ih = (const float*)d_in[6];
    const float* b_hh = (const float*)d_in[7];
    float* out = (float*)d_out;

    static bool attr_set = false;
    if (!attr_set) {
        cudaFuncSetAttribute(lstm_persist,
                             cudaFuncAttributeMaxDynamicSharedMemorySize, SMEM_TOTAL);
        attr_set = true;
    }

    // 3 dummies steer ncu (-s 5 -c 1): 6th launch = lstm_persist
    dummy_kernel<<<1, 32>>>();
    dummy_kernel<<<1, 32>>>();
    dummy_kernel<<<1, 32>>>();

    proj_kernel<<<dim3(16, 34), 256>>>(lemb, semb, W_ih, b_ih, b_hh);
    wconv_kernel<<<2048, 256>>>(W_hh);

    lstm_persist<<<dim3(64, 2), THREADS, SMEM_TOTAL>>>(lseq, sseq, out);
}